// round 6
// baseline (speedup 1.0000x reference)
#include <cuda_runtime.h>

#define OUT_DIM 8192
#define IN_DIM  8192
#define BATCH   32
// reference: new_w = clip(w + LR * (sum_b post*pre)/B), LR=0.01, B=32
#define LRB (0.01f / 32.0f)

// Packed dual-FMA: d = a*b + d elementwise on two packed f32 lanes (FFMA2).
static __device__ __forceinline__ void ffma2(unsigned long long &d,
                                             unsigned long long a,
                                             unsigned long long b) {
    asm("fma.rn.f32x2 %0, %1, %2, %3;" : "=l"(d) : "l"(a), "l"(b), "l"(d));
}

// Block tile: 32 (o) x 256 (i), 256 threads (8 warps).
// Thread tile: 4 (o) x 8 (i) as 4 float2 pairs; warp covers all 256 i.
//   o = o0 + warp*4 + r            (r = 0..3)
//   i = i0 + 2*lane + 64*c         (c = 0..3, each c is a float2 pair)
__global__ __launch_bounds__(256) void stdp_fused_kernel(
    const float* __restrict__ W,
    const float* __restrict__ pre,
    const float* __restrict__ post,
    float* __restrict__ Wout)
{
    __shared__ float  pre_s[BATCH][256];    // 32 KB, i-contiguous per b
    __shared__ float2 postd_s[BATCH][32];   //  8 KB, {p,p} duplicated for f32x2

    const int t    = threadIdx.x;
    const int lane = t & 31;
    const int warp = t >> 5;
    const int o0   = blockIdx.y * 32;
    const int i0   = blockIdx.x * 256;

    // --- stage pre tile [32 b][256 i] via float4 (coalesced) ---
    for (int idx = t; idx < BATCH * 64; idx += 256) {
        int b = idx >> 6;
        int j = idx & 63;
        float4 v = *(const float4*)(pre + (size_t)b * IN_DIM + i0 + j * 4);
        *(float4*)&pre_s[b][j * 4] = v;
    }
    // --- stage post tile duplicated: postd_s[b][o'] = {post[b,o0+o'], same} ---
    for (int idx = t; idx < BATCH * 32; idx += 256) {
        int b = idx >> 5;
        int o = idx & 31;
        float v = post[(size_t)b * OUT_DIM + o0 + o];
        postd_s[b][o] = make_float2(v, v);
    }
    __syncthreads();

    unsigned long long acc[4][4];  // [r][c], each = two f32 accumulators (i, i+1)
#pragma unroll
    for (int r = 0; r < 4; ++r)
#pragma unroll
        for (int c = 0; c < 4; ++c) acc[r][c] = 0ULL;  // {0.0f, 0.0f}

    const int ob = warp * 4;
#pragma unroll 8
    for (int b = 0; b < BATCH; ++b) {
        unsigned long long p[4], q[4];
#pragma unroll
        for (int r = 0; r < 4; ++r)   // broadcast load (conflict-free, N=1)
            p[r] = *(const unsigned long long*)&postd_s[b][ob + r];
#pragma unroll
        for (int c = 0; c < 4; ++c)   // lanes hit consecutive 8B -> conflict-free
            q[c] = *(const unsigned long long*)&pre_s[b][2 * lane + 64 * c];
#pragma unroll
        for (int r = 0; r < 4; ++r)
#pragma unroll
            for (int c = 0; c < 4; ++c)
                ffma2(acc[r][c], p[r], q[c]);
    }

    // --- fused epilogue: w + (LR/B)*delta, clip [0,1], coalesced float2 ---
#pragma unroll
    for (int r = 0; r < 4; ++r) {
        size_t o = (size_t)(o0 + ob + r);
        const float2* wrow = (const float2*)(W    + o * IN_DIM + i0);
        float2*       orow = (float2*)      (Wout + o * IN_DIM + i0);
#pragma unroll
        for (int c = 0; c < 4; ++c) {
            int j = lane + 32 * c;           // float2 pair index -> i = i0 + 2j
            float2 wv = wrow[j];
            float2 d  = *(float2*)&acc[r][c];
            float x = fminf(fmaxf(fmaf(d.x, LRB, wv.x), 0.0f), 1.0f);
            float y = fminf(fmaxf(fmaf(d.y, LRB, wv.y), 0.0f), 1.0f);
            orow[j] = make_float2(x, y);
        }
    }
}

extern "C" void kernel_launch(void* const* d_in, const int* in_sizes, int n_in,
                              void* d_out, int out_size) {
    const float* W    = (const float*)d_in[0];  // weights [8192, 8192]
    const float* pre  = (const float*)d_in[1];  // pre_activity [32, 8192]
    const float* post = (const float*)d_in[2];  // post_activity [32, 8192]
    float* out = (float*)d_out;                 // [8192, 8192]

    dim3 grid(IN_DIM / 256, OUT_DIM / 32);      // (32, 256)
    stdp_fused_kernel<<<grid, 256>>>(W, pre, post, out);
}